// round 6
// baseline (speedup 1.0000x reference)
#include <cuda_runtime.h>
#include <cstdint>

// CanineEmbeddings: multi-hash bucket embedding + concat + LayerNorm.
//   input_ids: [8, 8192] int64 (or int32 if jax x64 off — probed inline)
//   tables:    [8, 16384, 96] f32  (50.3 MB, L2-resident)
//   ln_scale/ln_bias: [768] f32
//   out:       [8, 8192, 768] f32  (201 MB, streamed .cs)
//
// Warp-per-token core (R5) + R6 change: each warp loops over TPW=8 tokens,
// hoisting all token-invariant state (scale/bias float4s, per-lane hash h,
// shard offset c, prime, table base pointer, id-width probe) out of the loop.
// Per token: 1 id load + 6 gather LDG.128 + shuffle reduce + 6 STG.128.cs.

#define NUM_HASHES      8
#define NUM_BUCKETS     16384
#define SHARD           96
#define HIDDEN          768
#define TOKENS          (8 * 8192)
#define WPB             8      // warps per block
#define TPW             8      // tokens per warp
#define LN_EPS          1e-6f

__constant__ uint32_t c_primes[NUM_HASHES] = {31u, 43u, 59u, 61u, 73u, 97u, 103u, 113u};

__global__ __launch_bounds__(32 * WPB)
void canine_emb_ln_kernel(const void* __restrict__ ids_raw,
                          const float* __restrict__ tables,
                          const float* __restrict__ ln_scale,
                          const float* __restrict__ ln_bias,
                          float* __restrict__ out) {
    const int lane   = threadIdx.x & 31;
    const int warp   = threadIdx.x >> 5;
    const int token0 = (blockIdx.x * WPB + warp) * TPW;

    // --- id-width probe, once per warp (uniform, L1-hit) ---
    // int32 data viewed as u64 has a nonzero id in the high word (w.p.
    // ~1 - 1e-6 each); 8 consecutive checks make a false "int64" verdict
    // require 8 independent zero ids: effectively never.
    const unsigned long long* ids64 = (const unsigned long long*)ids_raw;
    bool is64 = true;
    #pragma unroll
    for (int i = 0; i < 8; i++) {
        if (ids64[i] > 0xFFFFFFFFull) is64 = false;
    }

    // --- token-invariant per-lane state (hoisted) ---
    // lane owns float4 indices j = k*32 + lane, k = 0..5
    float4        sc[6], bi[6];
    const float4* base[6];            // &tables[h][0][c*4] as float4*
    uint32_t      pk[6];              // prime for this lane's h at slice k
    #pragma unroll
    for (int k = 0; k < 6; k++) {
        const int j = k * 32 + lane;
        const int h = j / 24;         // hash/shard index 0..7
        const int c = j - h * 24;     // float4 offset within 96-float row
        sc[k]   = __ldg((const float4*)ln_scale + j);
        bi[k]   = __ldg((const float4*)ln_bias  + j);
        pk[k]   = c_primes[h];
        base[k] = (const float4*)tables + (size_t)h * NUM_BUCKETS * (SHARD / 4) + c;
    }

    // --- token loop ---
    for (int t = 0; t < TPW; t++) {
        const int token = token0 + t;

        uint32_t id;
        if (is64) id = (uint32_t)ids64[token];
        else      id = ((const uint32_t*)ids_raw)[token];
        const uint32_t idp1 = id + 1u;

        // 6 independent gathers (MLP=6), 3 ALU ops each
        float4 v[6];
        #pragma unroll
        for (int k = 0; k < 6; k++) {
            const uint32_t bucket = (idp1 * pk[k]) & (NUM_BUCKETS - 1u);
            v[k] = __ldg(base[k] + bucket * (SHARD / 4));
        }

        // mean / var via warp shuffle (barrier-free)
        float s = 0.f, sq = 0.f;
        #pragma unroll
        for (int k = 0; k < 6; k++) {
            s  += v[k].x + v[k].y + v[k].z + v[k].w;
            sq += v[k].x * v[k].x + v[k].y * v[k].y
                + v[k].z * v[k].z + v[k].w * v[k].w;
        }
        #pragma unroll
        for (int o = 16; o > 0; o >>= 1) {
            s  += __shfl_xor_sync(0xFFFFFFFFu, s,  o);
            sq += __shfl_xor_sync(0xFFFFFFFFu, sq, o);
        }
        const float inv_n = 1.0f / (float)HIDDEN;
        const float mean  = s * inv_n;
        const float rstd  = rsqrtf(sq * inv_n - mean * mean + LN_EPS);

        // normalize + affine, streaming coalesced stores
        float4* out4 = (float4*)out + (size_t)token * (HIDDEN / 4) + lane;
        #pragma unroll
        for (int k = 0; k < 6; k++) {
            float4 o4;
            o4.x = (v[k].x - mean) * rstd * sc[k].x + bi[k].x;
            o4.y = (v[k].y - mean) * rstd * sc[k].y + bi[k].y;
            o4.z = (v[k].z - mean) * rstd * sc[k].z + bi[k].z;
            o4.w = (v[k].w - mean) * rstd * sc[k].w + bi[k].w;
            __stcs(out4 + k * 32, o4);
        }
    }
}

extern "C" void kernel_launch(void* const* d_in, const int* in_sizes, int n_in,
                              void* d_out, int out_size) {
    const void*  ids    = d_in[0];                 // [8, 8192] int32 or int64
    const float* tables = (const float*)d_in[1];   // [8, 16384, 96]
    const float* ln_s   = (const float*)d_in[2];   // [768]
    const float* ln_b   = (const float*)d_in[3];   // [768]
    float*       out    = (float*)d_out;           // [8, 8192, 768]

    canine_emb_ln_kernel<<<TOKENS / (WPB * TPW), 32 * WPB>>>(
        ids, tables, ln_s, ln_b, out);
}